// round 4
// baseline (speedup 1.0000x reference)
#include <cuda_runtime.h>
#include <math.h>
#include <stdint.h>

// Problem constants
#define TOKENS  16384
#define DMODEL  1024
#define NEXP    8
#define CAP     2048
#define BATCH   8
#define SEQ     2048

// ---------------- scratch (device globals; no allocation allowed) ----------
__device__ float g_h   [TOKENS * DMODEL];   // dense pre-layer output (64 MB)
__device__ float g_o2  [TOKENS * DMODEL];   // MoE layer 2 output     (64 MB)
__device__ float g_o3  [TOKENS * DMODEL];   // MoE layer 3 output     (64 MB)
__device__ int   g_idx [TOKENS];            // expert per token
__device__ float g_gval[TOKENS];            // softmax gate value at argmax
__device__ float g_gsc [TOKENS];            // gate * keep
__device__ int   g_inv [NEXP * CAP];        // expert slot -> token id (-1 empty)
__device__ float g_part[BATCH * 16 * DMODEL];
__device__ float g_sent[BATCH * DMODEL];

// ---------------- SGEMM: C[M,N] = gather(A)[M,K] @ B[K,N] + bias, scatter ---
// rowmap == nullptr : dense.  C row m = acc + bias.
// rowmap != nullptr : A row = rowmap[z*M+m] (token id, <0 => zero row);
//                     epilogue writes C[tok,:] = (acc + bias) * scale[tok].
// blockIdx.z selects expert: B += z*K*N, bias += z*N.
#define BM 128
#define BN 128
#define BK 16
#define TM 8
#define TN 8

__global__ __launch_bounds__(256) void sgemm_k(
    const float* __restrict__ A, const float* __restrict__ B,
    const float* __restrict__ bias, float* __restrict__ C,
    const int* __restrict__ rowmap, const float* __restrict__ scale,
    int M, int K, int N)
{
    __shared__ float As[BK][BM];
    __shared__ float Bs[BK][BN];

    const int e = blockIdx.z;
    const float* Bmat = B    + (size_t)e * K * N;
    const float* bvec = bias + (size_t)e * N;
    const int*   rmap = rowmap ? rowmap + (size_t)e * M : nullptr;

    const int mBase = blockIdx.y * BM;
    const int nBase = blockIdx.x * BN;
    const int tid = threadIdx.x;

    // A-load mapping: 256 thr x (2 rows x float4)
    const int aRow = tid >> 2;          // 0..63
    const int aCol = (tid & 3) * 4;     // 0,4,8,12
    int gRow0, gRow1;
    if (rmap) { gRow0 = rmap[mBase + aRow]; gRow1 = rmap[mBase + aRow + 64]; }
    else      { gRow0 = mBase + aRow;       gRow1 = mBase + aRow + 64; }

    // B-load mapping
    const int bRow = tid >> 5;          // 0..7 (rows bRow, bRow+8)
    const int bCol = (tid & 31) * 4;

    const int ty = tid >> 4, tx = tid & 15;

    float acc[TM][TN];
#pragma unroll
    for (int i = 0; i < TM; i++)
#pragma unroll
        for (int j = 0; j < TN; j++) acc[i][j] = 0.f;

    for (int k0 = 0; k0 < K; k0 += BK) {
        float4 a0 = make_float4(0.f, 0.f, 0.f, 0.f), a1 = a0;
        if (gRow0 >= 0) a0 = *(const float4*)&A[(size_t)gRow0 * K + k0 + aCol];
        if (gRow1 >= 0) a1 = *(const float4*)&A[(size_t)gRow1 * K + k0 + aCol];
        float4 b0 = *(const float4*)&Bmat[(size_t)(k0 + bRow)     * N + nBase + bCol];
        float4 b1 = *(const float4*)&Bmat[(size_t)(k0 + bRow + 8) * N + nBase + bCol];

        As[aCol + 0][aRow] = a0.x; As[aCol + 1][aRow] = a0.y;
        As[aCol + 2][aRow] = a0.z; As[aCol + 3][aRow] = a0.w;
        As[aCol + 0][aRow + 64] = a1.x; As[aCol + 1][aRow + 64] = a1.y;
        As[aCol + 2][aRow + 64] = a1.z; As[aCol + 3][aRow + 64] = a1.w;
        *(float4*)&Bs[bRow][bCol]     = b0;
        *(float4*)&Bs[bRow + 8][bCol] = b1;
        __syncthreads();

#pragma unroll
        for (int k = 0; k < BK; k++) {
            float ar[TM], br[TN];
            *(float4*)&ar[0] = *(const float4*)&As[k][ty * TM];
            *(float4*)&ar[4] = *(const float4*)&As[k][ty * TM + 4];
            *(float4*)&br[0] = *(const float4*)&Bs[k][tx * TN];
            *(float4*)&br[4] = *(const float4*)&Bs[k][tx * TN + 4];
#pragma unroll
            for (int i = 0; i < TM; i++)
#pragma unroll
                for (int j = 0; j < TN; j++) acc[i][j] += ar[i] * br[j];
        }
        __syncthreads();
    }

    // epilogue
#pragma unroll
    for (int i = 0; i < TM; i++) {
        const int m = mBase + ty * TM + i;
        int orow; float sc = 1.f;
        if (rmap) {
            const int tok = rmap[m];
            if (tok < 0) continue;
            orow = tok; sc = scale[tok];
        } else {
            orow = m;
        }
        float* crow = C + (size_t)orow * N + nBase + tx * TN;
        const float* brow = bvec + nBase + tx * TN;
#pragma unroll
        for (int j = 0; j < TN; j++) crow[j] = (acc[i][j] + brow[j]) * sc;
    }
}

// ---------------- gating: softmax(act @ Wg), argmax, gate value ------------
// one warp per token, 8 warps / block, Wg staged transposed in smem
__global__ __launch_bounds__(256) void gate_k(
    const float* __restrict__ act, const float* __restrict__ Wg,
    int* __restrict__ idx, float* __restrict__ gval)
{
    __shared__ float sWgT[NEXP][DMODEL];    // 32 KB
    const int tid = threadIdx.x;
    for (int i = tid; i < DMODEL * NEXP; i += 256) {
        const int k = i >> 3, e = i & 7;
        sWgT[e][k] = Wg[i];
    }
    __syncthreads();

    const int w = tid >> 5, lane = tid & 31;
    const int t = blockIdx.x * 8 + w;
    const float* arow = act + (size_t)t * DMODEL;

    float a8[NEXP];
#pragma unroll
    for (int e = 0; e < NEXP; e++) a8[e] = 0.f;
    for (int k = lane; k < DMODEL; k += 32) {
        const float a = arow[k];
#pragma unroll
        for (int e = 0; e < NEXP; e++) a8[e] += a * sWgT[e][k];
    }
#pragma unroll
    for (int e = 0; e < NEXP; e++)
#pragma unroll
        for (int off = 16; off > 0; off >>= 1)
            a8[e] += __shfl_xor_sync(0xffffffffu, a8[e], off);

    if (lane == 0) {
        float mx = a8[0]; int am = 0;
#pragma unroll
        for (int e = 1; e < NEXP; e++)
            if (a8[e] > mx) { mx = a8[e]; am = e; }   // first-max on ties (== jnp.argmax)
        float s = 0.f;
#pragma unroll
        for (int e = 0; e < NEXP; e++) s += __expf(a8[e] - mx);
        idx[t]  = am;
        gval[t] = 1.f / s;                            // exp(0)/sum
    }
}

// ---------------- capacity scan (single block, deterministic) --------------
#define TPT (TOKENS / 256)   // 64 tokens per thread
__global__ __launch_bounds__(256) void scan_k(
    const int* __restrict__ idx, const float* __restrict__ gval,
    float* __restrict__ gsc, int* __restrict__ invmap)
{
    __shared__ int scnt[256][NEXP];
    const int tid = threadIdx.x;
    const int t0 = tid * TPT;

    int cnt[NEXP];
#pragma unroll
    for (int e = 0; e < NEXP; e++) cnt[e] = 0;
    for (int i = 0; i < TPT; i++) cnt[idx[t0 + i]]++;
#pragma unroll
    for (int e = 0; e < NEXP; e++) scnt[tid][e] = cnt[e];
    __syncthreads();

    if (tid < NEXP) {       // exclusive scan per expert over the 256 threads
        int run = 0;
        for (int j = 0; j < 256; j++) { int c = scnt[j][tid]; scnt[j][tid] = run; run += c; }
    }
    __syncthreads();

    int run[NEXP];
#pragma unroll
    for (int e = 0; e < NEXP; e++) run[e] = scnt[tid][e];
    for (int i = 0; i < TPT; i++) {
        const int t = t0 + i;
        const int e = idx[t];
        const int loc = run[e]++;
        if (loc < CAP) { gsc[t] = gval[t]; invmap[e * CAP + loc] = t; }
        else           { gsc[t] = 0.f; }
    }
}

// ---------------- utility kernels -----------------------------------------
__global__ void fillneg_k(int* __restrict__ p, int n) {
    int i = blockIdx.x * blockDim.x + threadIdx.x;
    if (i < n) p[i] = -1;
}
__global__ void zero_k(float4* __restrict__ p, int n4) {
    for (int i = blockIdx.x * blockDim.x + threadIdx.x; i < n4; i += gridDim.x * blockDim.x)
        p[i] = make_float4(0.f, 0.f, 0.f, 0.f);
}

// ---------------- residual + mean over S (two-stage, deterministic) --------
__global__ __launch_bounds__(128) void meanpart_k(
    const float* __restrict__ h, const float* __restrict__ o, float* __restrict__ part)
{
    const int d = blockIdx.x * 128 + threadIdx.x;
    const int b = blockIdx.y, sc = blockIdx.z;
    const int base = b * SEQ + sc * 128;
    float s = 0.f;
#pragma unroll 4
    for (int r = 0; r < 128; r++) {
        const size_t off = (size_t)(base + r) * DMODEL + d;
        s += h[off] + o[off];
    }
    part[(size_t)(b * 16 + sc) * DMODEL + d] = s;
}
__global__ __launch_bounds__(128) void meanfin_k(
    const float* __restrict__ part, float* __restrict__ sent)
{
    const int d = blockIdx.x * 128 + threadIdx.x;
    const int b = blockIdx.y;
    float s = 0.f;
#pragma unroll
    for (int c = 0; c < 16; c++) s += part[(size_t)(b * 16 + c) * DMODEL + d];
    sent[(size_t)b * DMODEL + d] = s * (1.f / (float)SEQ);
}

// ---------------- loss: -mean_b log_softmax(sent[b])[y[b]] -----------------
__global__ __launch_bounds__(1024) void loss_k(
    const float* __restrict__ sent, const int* __restrict__ y, float* __restrict__ out)
{
    __shared__ float red[1024];
    __shared__ float s_loss;
    const int tid = threadIdx.x;
    if (tid == 0) s_loss = 0.f;
    __syncthreads();

    for (int b = 0; b < BATCH; b++) {
        const float v = sent[(size_t)b * DMODEL + tid];
        red[tid] = v; __syncthreads();
        for (int s = 512; s > 0; s >>= 1) {
            if (tid < s) red[tid] = fmaxf(red[tid], red[tid + s]);
            __syncthreads();
        }
        const float mx = red[0]; __syncthreads();
        red[tid] = expf(v - mx); __syncthreads();
        for (int s = 512; s > 0; s >>= 1) {
            if (tid < s) red[tid] += red[tid + s];
            __syncthreads();
        }
        if (tid == 0) {
            const float lse = mx + logf(red[0]);
            s_loss += sent[(size_t)b * DMODEL + y[b]] - lse;
        }
        __syncthreads();
    }
    if (tid == 0) out[0] = -s_loss * (1.f / (float)BATCH);
}

// ---------------- launcher --------------------------------------------------
static void moe_layer(const float* act_in, const float* Wg, const float* We,
                      const float* be, float* act_out,
                      int* p_idx, float* p_gval, float* p_gsc, int* p_inv)
{
    gate_k<<<TOKENS / 8, 256>>>(act_in, Wg, p_idx, p_gval);
    fillneg_k<<<(NEXP * CAP + 255) / 256, 256>>>(p_inv, NEXP * CAP);
    scan_k<<<1, 256>>>(p_idx, p_gval, p_gsc, p_inv);
    zero_k<<<2048, 256>>>((float4*)act_out, TOKENS * DMODEL / 4);
    dim3 ggrid(DMODEL / BN, CAP / BM, NEXP);
    sgemm_k<<<ggrid, 256>>>(act_in, We, be, act_out, p_inv, p_gsc,
                            CAP, DMODEL, DMODEL);
}

extern "C" void kernel_launch(void* const* d_in, const int* in_sizes, int n_in,
                              void* d_out, int out_size)
{
    const float* x   = (const float*)d_in[0];
    const int*   y   = (const int*)  d_in[1];
    const float* W1  = (const float*)d_in[2];
    const float* b1  = (const float*)d_in[3];
    const float* Wg2 = (const float*)d_in[4];
    const float* We2 = (const float*)d_in[5];
    const float* be2 = (const float*)d_in[6];
    const float* Wg3 = (const float*)d_in[7];
    const float* We3 = (const float*)d_in[8];
    const float* be3 = (const float*)d_in[9];
    float* out = (float*)d_out;

    float *p_h, *p_o2, *p_o3, *p_gval, *p_gsc, *p_part, *p_sent;
    int   *p_idx, *p_inv;
    cudaGetSymbolAddress((void**)&p_h,    g_h);
    cudaGetSymbolAddress((void**)&p_o2,   g_o2);
    cudaGetSymbolAddress((void**)&p_o3,   g_o3);
    cudaGetSymbolAddress((void**)&p_idx,  g_idx);
    cudaGetSymbolAddress((void**)&p_gval, g_gval);
    cudaGetSymbolAddress((void**)&p_gsc,  g_gsc);
    cudaGetSymbolAddress((void**)&p_inv,  g_inv);
    cudaGetSymbolAddress((void**)&p_part, g_part);
    cudaGetSymbolAddress((void**)&p_sent, g_sent);

    // 1) dense pre-layer: h = x @ W1 + b1
    {
        dim3 grid(DMODEL / BN, TOKENS / BM, 1);
        sgemm_k<<<grid, 256>>>(x, W1, b1, p_h, nullptr, nullptr,
                               TOKENS, DMODEL, DMODEL);
    }
    // 2) MoE layer 2: h -> o2
    moe_layer(p_h, Wg2, We2, be2, p_o2, p_idx, p_gval, p_gsc, p_inv);
    // 3) MoE layer 3: o2 -> o3
    moe_layer(p_o2, Wg3, We3, be3, p_o3, p_idx, p_gval, p_gsc, p_inv);
    // 4) residual + mean over S
    {
        dim3 g1(DMODEL / 128, BATCH, 16);
        meanpart_k<<<g1, 128>>>(p_h, p_o3, p_part);
        dim3 g2(DMODEL / 128, BATCH);
        meanfin_k<<<g2, 128>>>(p_part, p_sent);
    }
    // 5) loss
    loss_k<<<1, 1024>>>(p_sent, y, out);
}

// round 8
// speedup vs baseline: 3.8006x; 3.8006x over previous
#include <cuda_runtime.h>
#include <math.h>
#include <stdint.h>

// Problem constants
#define TOKENS  16384
#define DMODEL  1024
#define NEXP    8
#define CAP     2048
#define BATCH   8
#define SEQ     2048

// ---------------- scratch (device globals; no allocation allowed) ----------
__device__ float g_h   [TOKENS * DMODEL];
__device__ float g_o2  [TOKENS * DMODEL];
__device__ float g_o3  [TOKENS * DMODEL];
__device__ int   g_idx [TOKENS];
__device__ float g_gval[TOKENS];
__device__ float g_gsc [TOKENS];
__device__ int   g_inv [NEXP * CAP];
__device__ int   g_ccnt[256 * NEXP];       // per-chunk expert counts / offsets
__device__ float g_part[BATCH * 16 * DMODEL];
__device__ float g_sent[BATCH * DMODEL];

// ---------------- cp.async helpers ----------------------------------------
__device__ __forceinline__ void cp16(void* dst, const void* src, bool p) {
    unsigned s = (unsigned)__cvta_generic_to_shared(dst);
    int sz = p ? 16 : 0;
    asm volatile("cp.async.cg.shared.global [%0], [%1], 16, %2;\n"
                 :: "r"(s), "l"(src), "r"(sz) : "memory");
}
#define CP_COMMIT() asm volatile("cp.async.commit_group;\n" ::: "memory")
#define CP_WAIT(n)  asm volatile("cp.async.wait_group %0;\n" :: "n"(n) : "memory")

__device__ __forceinline__ void mma_tf32(float* d, const uint32_t* a, const uint32_t* b) {
    asm volatile(
        "mma.sync.aligned.m16n8k8.row.col.f32.tf32.tf32.f32 "
        "{%0,%1,%2,%3}, {%4,%5,%6,%7}, {%8,%9}, {%0,%1,%2,%3};\n"
        : "+f"(d[0]), "+f"(d[1]), "+f"(d[2]), "+f"(d[3])
        : "r"(a[0]), "r"(a[1]), "r"(a[2]), "r"(a[3]), "r"(b[0]), "r"(b[1]));
}

// ---------------- TF32 tensor-core GEMM ------------------------------------
// C[M,N] = gather(A)[M,K] @ B[K,N] + bias   (optionally scale+scatter by token)
// rowmap==nullptr: dense (row m -> C row m).
// rowmap!=nullptr: A row = rowmap[z*M+m] (token id, <0 => zero row / skip);
//                  epilogue writes C[tok,:] = (acc + bias) * scale[tok].
// blockIdx.z selects expert: B += z*K*N, bias += z*N.
#define BM  128
#define BN  128
#define BKT 16

__global__ __launch_bounds__(256, 2) void tgemm_k(
    const float* __restrict__ A, const float* __restrict__ B,
    const float* __restrict__ bias, float* __restrict__ C,
    const int* __restrict__ rowmap, const float* __restrict__ scale,
    int M, int K, int N)
{
    __shared__ float As[2][BM][BKT + 4];   // row stride 20 floats (80B, 16B-aligned)
    __shared__ float Bs[2][BKT][BN + 8];   // row stride 136 floats (544B)

    const int e = blockIdx.z;
    const float* Bmat = B    + (size_t)e * K * N;
    const float* bvec = bias + (size_t)e * N;
    const int*   rmap = rowmap ? rowmap + (size_t)e * M : nullptr;

    const int mBase = blockIdx.y * BM;
    const int nBase = blockIdx.x * BN;
    const int tid = threadIdx.x;

    // ---- global->smem load mapping (per thread: 2 A float4, 2 B float4) ----
    const int ar0 = tid >> 2;            // A rows 0..63 (+64)
    const int ar1 = ar0 + 64;
    const int ac  = (tid & 3) * 4;       // k offset 0,4,8,12
    int gRow0, gRow1;
    if (rmap) { gRow0 = rmap[mBase + ar0]; gRow1 = rmap[mBase + ar1]; }
    else      { gRow0 = mBase + ar0;       gRow1 = mBase + ar1; }
    const bool ap0 = gRow0 >= 0, ap1 = gRow1 >= 0;
    const float* aSrc0 = A + (size_t)(ap0 ? gRow0 : 0) * K + ac;
    const float* aSrc1 = A + (size_t)(ap1 ? gRow1 : 0) * K + ac;

    const int br0 = tid >> 5;            // B k-rows 0..7 (+8)
    const int br1 = br0 + 8;
    const int bc  = (tid & 31) * 4;
    const float* bSrc0 = Bmat + (size_t)br0 * N + nBase + bc;
    const float* bSrc1 = Bmat + (size_t)br1 * N + nBase + bc;

    auto load_stage = [&](int k0, int buf) {
        cp16(&As[buf][ar0][ac], aSrc0 + k0, ap0);
        cp16(&As[buf][ar1][ac], aSrc1 + k0, ap1);
        cp16(&Bs[buf][br0][bc], bSrc0 + (size_t)k0 * N, true);
        cp16(&Bs[buf][br1][bc], bSrc1 + (size_t)k0 * N, true);
    };

    // ---- warp / fragment mapping ----
    const int wid  = tid >> 5, lane = tid & 31;
    const int wm = (wid >> 2) * 64;      // warp tile: 64 (M) x 32 (N)
    const int wn = (wid & 3) * 32;
    const int r = lane >> 2;             // groupID
    const int c = lane & 3;              // threadID in group

    float acc[4][4][4];
#pragma unroll
    for (int i = 0; i < 4; i++)
#pragma unroll
        for (int j = 0; j < 4; j++)
#pragma unroll
            for (int q = 0; q < 4; q++) acc[i][j][q] = 0.f;

    const int nk = K / BKT;
    load_stage(0, 0);
    CP_COMMIT();

    for (int kt = 0; kt < nk; kt++) {
        const int buf = kt & 1;
        if (kt + 1 < nk) {
            load_stage((kt + 1) * BKT, buf ^ 1);
            CP_COMMIT();
            CP_WAIT(1);
        } else {
            CP_WAIT(0);
        }
        __syncthreads();

#pragma unroll
        for (int ks = 0; ks < BKT; ks += 8) {
            uint32_t af[4][4], bf[4][2];
#pragma unroll
            for (int mi = 0; mi < 4; mi++) {
                const int m0 = wm + mi * 16 + r;
                af[mi][0] = __float_as_uint(As[buf][m0    ][ks + c]);
                af[mi][1] = __float_as_uint(As[buf][m0 + 8][ks + c]);
                af[mi][2] = __float_as_uint(As[buf][m0    ][ks + c + 4]);
                af[mi][3] = __float_as_uint(As[buf][m0 + 8][ks + c + 4]);
            }
#pragma unroll
            for (int ni = 0; ni < 4; ni++) {
                const int n0 = wn + ni * 8 + r;
                bf[ni][0] = __float_as_uint(Bs[buf][ks + c    ][n0]);
                bf[ni][1] = __float_as_uint(Bs[buf][ks + c + 4][n0]);
            }
#pragma unroll
            for (int mi = 0; mi < 4; mi++)
#pragma unroll
                for (int ni = 0; ni < 4; ni++)
                    mma_tf32(acc[mi][ni], af[mi], bf[ni]);
        }
        __syncthreads();
    }

    // ---- epilogue: bias (+scale) and (scatter-)store; 2 cols/thread/tile ----
    // hoist bias loads: same 8 columns for all mi
    float bx[4], by[4];
#pragma unroll
    for (int ni = 0; ni < 4; ni++) {
        const int col = nBase + wn + ni * 8 + c * 2;
        bx[ni] = bvec[col]; by[ni] = bvec[col + 1];
    }
#pragma unroll
    for (int mi = 0; mi < 4; mi++) {
        const int mloc0 = mBase + wm + mi * 16 + r;
        const int mloc1 = mloc0 + 8;
        int orow0, orow1; float sc0 = 1.f, sc1 = 1.f;
        bool v0 = true, v1 = true;
        if (rmap) {
            const int t0 = rmap[mloc0], t1 = rmap[mloc1];
            v0 = t0 >= 0; v1 = t1 >= 0;
            orow0 = v0 ? t0 : 0; orow1 = v1 ? t1 : 0;
            if (v0) sc0 = scale[t0];
            if (v1) sc1 = scale[t1];
        } else {
            orow0 = mloc0; orow1 = mloc1;
        }
#pragma unroll
        for (int ni = 0; ni < 4; ni++) {
            const int col = nBase + wn + ni * 8 + c * 2;
            if (v0) {
                float2 o; o.x = (acc[mi][ni][0] + bx[ni]) * sc0;
                          o.y = (acc[mi][ni][1] + by[ni]) * sc0;
                *(float2*)&C[(size_t)orow0 * N + col] = o;
            }
            if (v1) {
                float2 o; o.x = (acc[mi][ni][2] + bx[ni]) * sc1;
                          o.y = (acc[mi][ni][3] + by[ni]) * sc1;
                *(float2*)&C[(size_t)orow1 * N + col] = o;
            }
        }
    }
}

// ---------------- gating: softmax(act @ Wg), argmax, gate value ------------
__global__ __launch_bounds__(256) void gate_k(
    const float* __restrict__ act, const float* __restrict__ Wg,
    int* __restrict__ idx, float* __restrict__ gval)
{
    __shared__ float sWgT[NEXP][DMODEL];
    const int tid = threadIdx.x;
    for (int i = tid; i < DMODEL * NEXP; i += 256) {
        const int k = i >> 3, e = i & 7;
        sWgT[e][k] = Wg[i];
    }
    __syncthreads();

    const int w = tid >> 5, lane = tid & 31;
    const int t = blockIdx.x * 8 + w;
    const float* arow = act + (size_t)t * DMODEL;

    float a8[NEXP];
#pragma unroll
    for (int e = 0; e < NEXP; e++) a8[e] = 0.f;
    for (int k = lane; k < DMODEL; k += 32) {
        const float a = arow[k];
#pragma unroll
        for (int e = 0; e < NEXP; e++) a8[e] += a * sWgT[e][k];
    }
#pragma unroll
    for (int e = 0; e < NEXP; e++)
#pragma unroll
        for (int off = 16; off > 0; off >>= 1)
            a8[e] += __shfl_xor_sync(0xffffffffu, a8[e], off);

    if (lane == 0) {
        float mx = a8[0]; int am = 0;
#pragma unroll
        for (int e = 1; e < NEXP; e++)
            if (a8[e] > mx) { mx = a8[e]; am = e; }   // first-max ties == jnp.argmax
        float s = 0.f;
#pragma unroll
        for (int e = 0; e < NEXP; e++) s += __expf(a8[e] - mx);
        idx[t]  = am;
        gval[t] = 1.f / s;
    }
}

// ---------------- capacity assignment: hist -> scan -> assign ---------------
// 256 chunks of 64 tokens each; warp per chunk.
__global__ __launch_bounds__(256) void hist_k(
    const int* __restrict__ idx, int* __restrict__ ccnt)
{
    const int gw   = (blockIdx.x * 256 + threadIdx.x) >> 5;   // chunk 0..255
    const int lane = threadIdx.x & 31;
    const int t0 = gw * 64;
    const int e0 = idx[t0 + lane], e1 = idx[t0 + 32 + lane];
    int cnt[NEXP];
#pragma unroll
    for (int e = 0; e < NEXP; e++) {
        unsigned m0 = __ballot_sync(0xffffffffu, e0 == e);
        unsigned m1 = __ballot_sync(0xffffffffu, e1 == e);
        cnt[e] = __popc(m0) + __popc(m1);
    }
    if (lane < NEXP) ccnt[gw * NEXP + lane] = cnt[lane];
}

// 1 block / 8 warps; warp e does an exclusive scan over 256 chunk counts.
__global__ __launch_bounds__(256) void scan2_k(int* __restrict__ ccnt)
{
    const int e = threadIdx.x >> 5, lane = threadIdx.x & 31;
    int carry = 0;
    for (int c0 = 0; c0 < 256; c0 += 32) {
        int v = ccnt[(c0 + lane) * NEXP + e];
        int s = v;
#pragma unroll
        for (int off = 1; off < 32; off <<= 1) {
            int n = __shfl_up_sync(0xffffffffu, s, off);
            if (lane >= off) s += n;
        }
        ccnt[(c0 + lane) * NEXP + e] = carry + s - v;   // exclusive
        carry += __shfl_sync(0xffffffffu, s, 31);
    }
}

__global__ __launch_bounds__(256) void assign_k(
    const int* __restrict__ idx, const float* __restrict__ gval,
    const int* __restrict__ ccnt, float* __restrict__ gsc,
    int* __restrict__ invmap)
{
    const int gw   = (blockIdx.x * 256 + threadIdx.x) >> 5;
    const int lane = threadIdx.x & 31;
    const int t0 = gw * 64;
    const int ta = t0 + lane, tb = t0 + 32 + lane;
    const int e0 = idx[ta], e1 = idx[tb];
    const unsigned lt = (1u << lane) - 1u;
    int rank0 = 0, rank1 = 0;
#pragma unroll
    for (int e = 0; e < NEXP; e++) {
        unsigned m0 = __ballot_sync(0xffffffffu, e0 == e);
        unsigned m1 = __ballot_sync(0xffffffffu, e1 == e);
        if (e0 == e) rank0 = __popc(m0 & lt);
        if (e1 == e) rank1 = __popc(m0) + __popc(m1 & lt);
    }
    const int loc0 = ccnt[gw * NEXP + e0] + rank0;
    const int loc1 = ccnt[gw * NEXP + e1] + rank1;
    if (loc0 < CAP) { gsc[ta] = gval[ta]; invmap[e0 * CAP + loc0] = ta; }
    else            { gsc[ta] = 0.f; }
    if (loc1 < CAP) { gsc[tb] = gval[tb]; invmap[e1 * CAP + loc1] = tb; }
    else            { gsc[tb] = 0.f; }
}

// ---------------- utility kernels -----------------------------------------
__global__ void fillneg_k(int* __restrict__ p, int n) {
    int i = blockIdx.x * blockDim.x + threadIdx.x;
    if (i < n) p[i] = -1;
}
// zero only dropped-token rows (kept rows are fully overwritten by scatter)
__global__ __launch_bounds__(128) void zerodrop_k(
    const float* __restrict__ gsc, float4* __restrict__ out)
{
    const int t = blockIdx.x;
    if (gsc[t] != 0.f) return;
    const float4 z = make_float4(0.f, 0.f, 0.f, 0.f);
    float4* row = out + (size_t)t * (DMODEL / 4);
#pragma unroll
    for (int i = threadIdx.x; i < DMODEL / 4; i += 128) row[i] = z;
}

// ---------------- residual + mean over S (two-stage, deterministic) --------
__global__ __launch_bounds__(128) void meanpart_k(
    const float* __restrict__ h, const float* __restrict__ o, float* __restrict__ part)
{
    const int d = blockIdx.x * 128 + threadIdx.x;
    const int b = blockIdx.y, sc = blockIdx.z;
    const int base = b * SEQ + sc * 128;
    float s = 0.f;
#pragma unroll 4
    for (int rr = 0; rr < 128; rr++) {
        const size_t off = (size_t)(base + rr) * DMODEL + d;
        s += h[off] + o[off];
    }
    part[(size_t)(b * 16 + sc) * DMODEL + d] = s;
}
__global__ __launch_bounds__(128) void meanfin_k(
    const float* __restrict__ part, float* __restrict__ sent)
{
    const int d = blockIdx.x * 128 + threadIdx.x;
    const int b = blockIdx.y;
    float s = 0.f;
#pragma unroll
    for (int cc = 0; cc < 16; cc++) s += part[(size_t)(b * 16 + cc) * DMODEL + d];
    sent[(size_t)b * DMODEL + d] = s * (1.f / (float)SEQ);
}

// ---------------- loss ------------------------------------------------------
__global__ __launch_bounds__(1024) void loss_k(
    const float* __restrict__ sent, const int* __restrict__ y, float* __restrict__ out)
{
    __shared__ float red[1024];
    __shared__ float s_loss;
    const int tid = threadIdx.x;
    if (tid == 0) s_loss = 0.f;
    __syncthreads();

    for (int b = 0; b < BATCH; b++) {
        const float v = sent[(size_t)b * DMODEL + tid];
        red[tid] = v; __syncthreads();
        for (int s = 512; s > 0; s >>= 1) {
            if (tid < s) red[tid] = fmaxf(red[tid], red[tid + s]);
            __syncthreads();
        }
        const float mx = red[0]; __syncthreads();
        red[tid] = expf(v - mx); __syncthreads();
        for (int s = 512; s > 0; s >>= 1) {
            if (tid < s) red[tid] += red[tid + s];
            __syncthreads();
        }
        if (tid == 0) {
            const float lse = mx + logf(red[0]);
            s_loss += sent[(size_t)b * DMODEL + y[b]] - lse;
        }
        __syncthreads();
    }
    if (tid == 0) out[0] = -s_loss * (1.f / (float)BATCH);
}

// ---------------- launcher --------------------------------------------------
static void moe_layer(const float* act_in, const float* Wg, const float* We,
                      const float* be, float* act_out,
                      int* p_idx, float* p_gval, float* p_gsc, int* p_inv, int* p_ccnt)
{
    gate_k   <<<TOKENS / 8, 256>>>(act_in, Wg, p_idx, p_gval);
    hist_k   <<<32, 256>>>(p_idx, p_ccnt);
    scan2_k  <<<1, 256>>>(p_ccnt);
    fillneg_k<<<(NEXP * CAP + 255) / 256, 256>>>(p_inv, NEXP * CAP);
    assign_k <<<32, 256>>>(p_idx, p_gval, p_ccnt, p_gsc, p_inv);
    zerodrop_k<<<TOKENS, 128>>>(p_gsc, (float4*)act_out);
    dim3 ggrid(DMODEL / BN, CAP / BM, NEXP);
    tgemm_k<<<ggrid, 256>>>(act_in, We, be, act_out, p_inv, p_gsc,
                            CAP, DMODEL, DMODEL);
}

extern "C" void kernel_launch(void* const* d_in, const int* in_sizes, int n_in,
                              void* d_out, int out_size)
{
    const float* x   = (const float*)d_in[0];
    const int*   y   = (const int*)  d_in[1];
    const float* W1  = (const float*)d_in[2];
    const float* b1  = (const float*)d_in[3];
    const float* Wg2 = (const float*)d_in[4];
    const float* We2 = (const float*)d_in[5];
    const float* be2 = (const float*)d_in[6];
    const float* Wg3 = (const float*)d_in[7];
    const float* We3 = (const float*)d_in[8];
    const float* be3 = (const float*)d_in[9];
    float* out = (float*)d_out;

    float *p_h, *p_o2, *p_o3, *p_gval, *p_gsc, *p_part, *p_sent;
    int   *p_idx, *p_inv, *p_ccnt;
    cudaGetSymbolAddress((void**)&p_h,    g_h);
    cudaGetSymbolAddress((void**)&p_o2,   g_o2);
    cudaGetSymbolAddress((void**)&p_o3,   g_o3);
    cudaGetSymbolAddress((void**)&p_idx,  g_idx);
    cudaGetSymbolAddress((void**)&p_gval, g_gval);
    cudaGetSymbolAddress((void**)&p_gsc,  g_gsc);
    cudaGetSymbolAddress((void**)&p_inv,  g_inv);
    cudaGetSymbolAddress((void**)&p_ccnt, g_ccnt);
    cudaGetSymbolAddress((void**)&p_part, g_part);
    cudaGetSymbolAddress((void**)&p_sent, g_sent);

    // 1) dense pre-layer: h = x @ W1 + b1
    {
        dim3 grid(DMODEL / BN, TOKENS / BM, 1);
        tgemm_k<<<grid, 256>>>(x, W1, b1, p_h, nullptr, nullptr,
                               TOKENS, DMODEL, DMODEL);
    }
    // 2) MoE layer 2: h -> o2
    moe_layer(p_h, Wg2, We2, be2, p_o2, p_idx, p_gval, p_gsc, p_inv, p_ccnt);
    // 3) MoE layer 3: o2 -> o3
    moe_layer(p_o2, Wg3, We3, be3, p_o3, p_idx, p_gval, p_gsc, p_inv, p_ccnt);
    // 4) residual + mean over S
    {
        dim3 g1(DMODEL / 128, BATCH, 16);
        meanpart_k<<<g1, 128>>>(p_h, p_o3, p_part);
        dim3 g2(DMODEL / 128, BATCH);
        meanfin_k<<<g2, 128>>>(p_part, p_sent);
    }
    // 5) loss
    loss_k<<<1, 1024>>>(p_sent, y, out);
}

// round 15
// speedup vs baseline: 5.2150x; 1.3721x over previous
#include <cuda_runtime.h>
#include <cuda_bf16.h>
#include <math.h>
#include <stdint.h>

// Problem constants
#define TOKENS  16384
#define DMODEL  1024
#define NEXP    8
#define CAP     2048
#define BATCH   8
#define SEQ     2048

// ---------------- scratch (device globals; no allocation allowed) ----------
__device__ __nv_bfloat16 g_xb [TOKENS * DMODEL];   // x in bf16
__device__ __nv_bfloat16 g_hb [TOKENS * DMODEL];   // dense layer out (bf16)
__device__ __nv_bfloat16 g_o2b[TOKENS * DMODEL];
__device__ __nv_bfloat16 g_o3b[TOKENS * DMODEL];
__device__ __nv_bfloat16 g_w1t[DMODEL * DMODEL];          // W1^T  [n][k] bf16
__device__ __nv_bfloat16 g_w2t[NEXP * DMODEL * DMODEL];   // We2^T [e][n][k]
__device__ __nv_bfloat16 g_w3t[NEXP * DMODEL * DMODEL];   // We3^T [e][n][k]
__device__ int   g_idx [TOKENS];
__device__ float g_gval[TOKENS];
__device__ float g_gsc [TOKENS];
__device__ int   g_inv [NEXP * CAP];
__device__ int   g_ccnt[256 * NEXP];
__device__ float g_part[BATCH * 16 * DMODEL];
__device__ float g_sent[BATCH * DMODEL];

// ---------------- cp.async helpers ----------------------------------------
__device__ __forceinline__ void cp16(void* dst, const void* src, bool p) {
    unsigned s = (unsigned)__cvta_generic_to_shared(dst);
    int sz = p ? 16 : 0;
    asm volatile("cp.async.cg.shared.global [%0], [%1], 16, %2;\n"
                 :: "r"(s), "l"(src), "r"(sz) : "memory");
}
#define CP_COMMIT() asm volatile("cp.async.commit_group;\n" ::: "memory")
#define CP_WAIT(n)  asm volatile("cp.async.wait_group %0;\n" :: "n"(n) : "memory")

__device__ __forceinline__ void mma_bf16(float* d, const uint32_t* a, const uint32_t* b) {
    asm volatile(
        "mma.sync.aligned.m16n8k16.row.col.f32.bf16.bf16.f32 "
        "{%0,%1,%2,%3}, {%4,%5,%6,%7}, {%8,%9}, {%0,%1,%2,%3};\n"
        : "+f"(d[0]), "+f"(d[1]), "+f"(d[2]), "+f"(d[3])
        : "r"(a[0]), "r"(a[1]), "r"(a[2]), "r"(a[3]), "r"(b[0]), "r"(b[1]));
}

// ---------------- bf16 tensor-core GEMM (legacy mma.sync path) --------------
// C[t,n] = (gather(A)[m,:] @ Bt[e][n][:]^T + bias[e,n]) * scale[t]  (bf16 out)
// A: [rows][K] bf16 row-major (K-major). Bt: [e][n][k] bf16 (K-major).
// rowmap==nullptr: dense. rowmap!=nullptr: A row = rowmap[z*M+m] (<0 => zero/skip),
// epilogue scatters to C[tok,:] scaled by scale[tok].
#define BM   128
#define BN   128
#define BKB  32
#define KPAD 8     // row stride 40 bf16 = 80 B (16B-aligned, conflict-free frags)

__global__ __launch_bounds__(256, 2) void bgemm_k(
    const __nv_bfloat16* __restrict__ A,
    const __nv_bfloat16* __restrict__ Bt,
    const float* __restrict__ bias,
    __nv_bfloat16* __restrict__ C,
    const int* __restrict__ rowmap,
    const float* __restrict__ scale, int Mrows)
{
    __shared__ __nv_bfloat16 As[2][BM][BKB + KPAD];
    __shared__ __nv_bfloat16 Bs[2][BN][BKB + KPAD];

    const int e = blockIdx.z;
    const __nv_bfloat16* Bm = Bt + (size_t)e * DMODEL * DMODEL;
    const float* bvec = bias + (size_t)e * DMODEL;
    const int* rmap = rowmap ? rowmap + (size_t)e * Mrows : nullptr;

    const int mBase = blockIdx.y * BM;
    const int nBase = blockIdx.x * BN;
    const int tid = threadIdx.x;

    // ---- global->smem mapping: per thread 2 A segs + 2 B segs (16B = 8 bf16)
    const int r0 = tid >> 2;          // rows 0..63 (+64)
    const int r1 = r0 + 64;
    const int sg = (tid & 3) * 8;     // k-elem offset 0,8,16,24
    int g0, g1;
    if (rmap) { g0 = rmap[mBase + r0]; g1 = rmap[mBase + r1]; }
    else      { g0 = mBase + r0;       g1 = mBase + r1; }
    const bool p0 = g0 >= 0, p1 = g1 >= 0;
    const __nv_bfloat16* aS0 = A  + (size_t)(p0 ? g0 : 0) * DMODEL + sg;
    const __nv_bfloat16* aS1 = A  + (size_t)(p1 ? g1 : 0) * DMODEL + sg;
    const __nv_bfloat16* bS0 = Bm + (size_t)(nBase + r0) * DMODEL + sg;
    const __nv_bfloat16* bS1 = Bm + (size_t)(nBase + r1) * DMODEL + sg;

    auto load_stage = [&](int k0, int buf) {
        cp16(&As[buf][r0][sg], aS0 + k0, p0);
        cp16(&As[buf][r1][sg], aS1 + k0, p1);
        cp16(&Bs[buf][r0][sg], bS0 + k0, true);
        cp16(&Bs[buf][r1][sg], bS1 + k0, true);
    };

    // ---- warp / fragment mapping: warp tile 64(M) x 32(N)
    const int wid = tid >> 5, lane = tid & 31;
    const int wm = (wid >> 2) * 64;
    const int wn = (wid & 3) * 32;
    const int r = lane >> 2;          // groupID 0..7
    const int c = lane & 3;           // threadID in group

    float acc[4][4][4];
#pragma unroll
    for (int i = 0; i < 4; i++)
#pragma unroll
        for (int j = 0; j < 4; j++)
#pragma unroll
            for (int q = 0; q < 4; q++) acc[i][j][q] = 0.f;

    const int nk = DMODEL / BKB;      // 32 chunks
    load_stage(0, 0);
    CP_COMMIT();

    for (int kt = 0; kt < nk; kt++) {
        const int buf = kt & 1;
        if (kt + 1 < nk) {
            load_stage((kt + 1) * BKB, buf ^ 1);
            CP_COMMIT();
            CP_WAIT(1);
        } else {
            CP_WAIT(0);
        }
        __syncthreads();

#pragma unroll
        for (int ks = 0; ks < BKB; ks += 16) {
            uint32_t af[4][4], bfr[4][2];
#pragma unroll
            for (int mi = 0; mi < 4; mi++) {
                const int m0 = wm + mi * 16 + r;
                af[mi][0] = *(const uint32_t*)&As[buf][m0    ][ks + 2 * c];
                af[mi][1] = *(const uint32_t*)&As[buf][m0 + 8][ks + 2 * c];
                af[mi][2] = *(const uint32_t*)&As[buf][m0    ][ks + 2 * c + 8];
                af[mi][3] = *(const uint32_t*)&As[buf][m0 + 8][ks + 2 * c + 8];
            }
#pragma unroll
            for (int ni = 0; ni < 4; ni++) {
                const int n0 = wn + ni * 8 + r;
                bfr[ni][0] = *(const uint32_t*)&Bs[buf][n0][ks + 2 * c];
                bfr[ni][1] = *(const uint32_t*)&Bs[buf][n0][ks + 2 * c + 8];
            }
#pragma unroll
            for (int mi = 0; mi < 4; mi++)
#pragma unroll
                for (int ni = 0; ni < 4; ni++)
                    mma_bf16(acc[mi][ni], af[mi], bfr[ni]);
        }
        __syncthreads();
    }

    // ---- epilogue: bias (+scale) -> bf16, (scatter-)store -------------------
    float bx[4], by[4];
#pragma unroll
    for (int ni = 0; ni < 4; ni++) {
        const int col = nBase + wn + ni * 8 + c * 2;
        bx[ni] = bvec[col]; by[ni] = bvec[col + 1];
    }
#pragma unroll
    for (int mi = 0; mi < 4; mi++) {
        const int mloc0 = mBase + wm + mi * 16 + r;
        const int mloc1 = mloc0 + 8;
        int orow0, orow1; float sc0 = 1.f, sc1 = 1.f;
        bool v0 = true, v1 = true;
        if (rmap) {
            const int t0 = rmap[mloc0], t1 = rmap[mloc1];
            v0 = t0 >= 0; v1 = t1 >= 0;
            orow0 = v0 ? t0 : 0; orow1 = v1 ? t1 : 0;
            if (v0) sc0 = scale[t0];
            if (v1) sc1 = scale[t1];
        } else {
            orow0 = mloc0; orow1 = mloc1;
        }
#pragma unroll
        for (int ni = 0; ni < 4; ni++) {
            const int col = nBase + wn + ni * 8 + c * 2;
            if (v0) {
                __nv_bfloat162 h2 = __float22bfloat162_rn(make_float2(
                    (acc[mi][ni][0] + bx[ni]) * sc0, (acc[mi][ni][1] + by[ni]) * sc0));
                *(uint32_t*)&C[(size_t)orow0 * DMODEL + col] = *(uint32_t*)&h2;
            }
            if (v1) {
                __nv_bfloat162 h2 = __float22bfloat162_rn(make_float2(
                    (acc[mi][ni][2] + bx[ni]) * sc1, (acc[mi][ni][3] + by[ni]) * sc1));
                *(uint32_t*)&C[(size_t)orow1 * DMODEL + col] = *(uint32_t*)&h2;
            }
        }
    }
}

// ---------------- fp32 -> bf16 convert (8 elems/thread/iter) ---------------
__global__ void cvt_k(const float4* __restrict__ src, uint4* __restrict__ dst, int n8)
{
    for (int i = blockIdx.x * blockDim.x + threadIdx.x; i < n8; i += gridDim.x * blockDim.x) {
        float4 a = src[2 * i], b = src[2 * i + 1];
        __nv_bfloat162 q0 = __float22bfloat162_rn(make_float2(a.x, a.y));
        __nv_bfloat162 q1 = __float22bfloat162_rn(make_float2(a.z, a.w));
        __nv_bfloat162 q2 = __float22bfloat162_rn(make_float2(b.x, b.y));
        __nv_bfloat162 q3 = __float22bfloat162_rn(make_float2(b.z, b.w));
        uint4 o;
        o.x = *(uint32_t*)&q0; o.y = *(uint32_t*)&q1;
        o.z = *(uint32_t*)&q2; o.w = *(uint32_t*)&q3;
        dst[i] = o;
    }
}

// ---------------- transpose + convert: dst[e][n][k] = bf16(src[e][k][n]) ----
__global__ __launch_bounds__(256) void tconv_k(
    const float* __restrict__ src, __nv_bfloat16* __restrict__ dst)
{
    __shared__ float t[32][33];
    const int e = blockIdx.z;
    src += (size_t)e * DMODEL * DMODEL;
    dst += (size_t)e * DMODEL * DMODEL;
    const int bx = blockIdx.x * 32, by = blockIdx.y * 32;
    const int tx = threadIdx.x & 31, ty = threadIdx.x >> 5;
#pragma unroll
    for (int i = 0; i < 4; i++)
        t[ty + 8 * i][tx] = src[(size_t)(by + ty + 8 * i) * DMODEL + bx + tx];
    __syncthreads();
#pragma unroll
    for (int i = 0; i < 4; i++)
        dst[(size_t)(bx + ty + 8 * i) * DMODEL + by + tx] =
            __float2bfloat16(t[tx][ty + 8 * i]);
}

// ---------------- gating (bf16 activations, fp32 math) ----------------------
__global__ __launch_bounds__(256) void gate_k(
    const __nv_bfloat16* __restrict__ act, const float* __restrict__ Wg,
    int* __restrict__ idx, float* __restrict__ gval)
{
    __shared__ float sWgT[NEXP][DMODEL];
    const int tid = threadIdx.x;
    for (int i = tid; i < DMODEL * NEXP; i += 256) {
        const int k = i >> 3, e = i & 7;
        sWgT[e][k] = Wg[i];
    }
    __syncthreads();

    const int w = tid >> 5, lane = tid & 31;
    const int t = blockIdx.x * 8 + w;
    const __nv_bfloat16* arow = act + (size_t)t * DMODEL;

    float a8[NEXP];
#pragma unroll
    for (int e = 0; e < NEXP; e++) a8[e] = 0.f;
    for (int k = lane; k < DMODEL; k += 32) {
        const float a = __bfloat162float(arow[k]);
#pragma unroll
        for (int e = 0; e < NEXP; e++) a8[e] += a * sWgT[e][k];
    }
#pragma unroll
    for (int e = 0; e < NEXP; e++)
#pragma unroll
        for (int off = 16; off > 0; off >>= 1)
            a8[e] += __shfl_xor_sync(0xffffffffu, a8[e], off);

    if (lane == 0) {
        float mx = a8[0]; int am = 0;
#pragma unroll
        for (int e = 1; e < NEXP; e++)
            if (a8[e] > mx) { mx = a8[e]; am = e; }   // first-max ties == jnp.argmax
        float s = 0.f;
#pragma unroll
        for (int e = 0; e < NEXP; e++) s += __expf(a8[e] - mx);
        idx[t]  = am;
        gval[t] = 1.f / s;
    }
}

// ---------------- capacity assignment: hist -> scan -> assign ---------------
__global__ __launch_bounds__(256) void hist_k(
    const int* __restrict__ idx, int* __restrict__ ccnt)
{
    const int gw   = (blockIdx.x * 256 + threadIdx.x) >> 5;
    const int lane = threadIdx.x & 31;
    const int t0 = gw * 64;
    const int e0 = idx[t0 + lane], e1 = idx[t0 + 32 + lane];
    int cnt[NEXP];
#pragma unroll
    for (int e = 0; e < NEXP; e++) {
        unsigned m0 = __ballot_sync(0xffffffffu, e0 == e);
        unsigned m1 = __ballot_sync(0xffffffffu, e1 == e);
        cnt[e] = __popc(m0) + __popc(m1);
    }
    if (lane < NEXP) ccnt[gw * NEXP + lane] = cnt[lane];
}

__global__ __launch_bounds__(256) void scan2_k(int* __restrict__ ccnt)
{
    const int e = threadIdx.x >> 5, lane = threadIdx.x & 31;
    int carry = 0;
    for (int c0 = 0; c0 < 256; c0 += 32) {
        int v = ccnt[(c0 + lane) * NEXP + e];
        int s = v;
#pragma unroll
        for (int off = 1; off < 32; off <<= 1) {
            int n = __shfl_up_sync(0xffffffffu, s, off);
            if (lane >= off) s += n;
        }
        ccnt[(c0 + lane) * NEXP + e] = carry + s - v;
        carry += __shfl_sync(0xffffffffu, s, 31);
    }
}

__global__ __launch_bounds__(256) void assign_k(
    const int* __restrict__ idx, const float* __restrict__ gval,
    const int* __restrict__ ccnt, float* __restrict__ gsc,
    int* __restrict__ invmap)
{
    const int gw   = (blockIdx.x * 256 + threadIdx.x) >> 5;
    const int lane = threadIdx.x & 31;
    const int t0 = gw * 64;
    const int ta = t0 + lane, tb = t0 + 32 + lane;
    const int e0 = idx[ta], e1 = idx[tb];
    const unsigned lt = (1u << lane) - 1u;
    int rank0 = 0, rank1 = 0;
#pragma unroll
    for (int e = 0; e < NEXP; e++) {
        unsigned m0 = __ballot_sync(0xffffffffu, e0 == e);
        unsigned m1 = __ballot_sync(0xffffffffu, e1 == e);
        if (e0 == e) rank0 = __popc(m0 & lt);
        if (e1 == e) rank1 = __popc(m0) + __popc(m1 & lt);
    }
    const int loc0 = ccnt[gw * NEXP + e0] + rank0;
    const int loc1 = ccnt[gw * NEXP + e1] + rank1;
    if (loc0 < CAP) { gsc[ta] = gval[ta]; invmap[e0 * CAP + loc0] = ta; }
    else            { gsc[ta] = 0.f; }
    if (loc1 < CAP) { gsc[tb] = gval[tb]; invmap[e1 * CAP + loc1] = tb; }
    else            { gsc[tb] = 0.f; }
}

// ---------------- utility kernels -----------------------------------------
__global__ void fillneg_k(int* __restrict__ p, int n) {
    int i = blockIdx.x * blockDim.x + threadIdx.x;
    if (i < n) p[i] = -1;
}
__global__ __launch_bounds__(128) void zerodropb_k(
    const float* __restrict__ gsc, uint4* __restrict__ out)
{
    const int t = blockIdx.x;
    if (gsc[t] != 0.f) return;
    const uint4 z = make_uint4(0, 0, 0, 0);
    uint4* row = out + (size_t)t * (DMODEL / 8);   // 1024 bf16 = 128 x uint4
    row[threadIdx.x] = z;
}

// ---------------- residual + mean over S (bf16 inputs) ----------------------
__global__ __launch_bounds__(128) void meanpartb_k(
    const __nv_bfloat16* __restrict__ h, const __nv_bfloat16* __restrict__ o,
    float* __restrict__ part)
{
    const int d = blockIdx.x * 128 + threadIdx.x;
    const int b = blockIdx.y, sc = blockIdx.z;
    const int base = b * SEQ + sc * 128;
    float s = 0.f;
#pragma unroll 4
    for (int rr = 0; rr < 128; rr++) {
        const size_t off = (size_t)(base + rr) * DMODEL + d;
        s += __bfloat162float(h[off]) + __bfloat162float(o[off]);
    }
    part[(size_t)(b * 16 + sc) * DMODEL + d] = s;
}
__global__ __launch_bounds__(128) void meanfin_k(
    const float* __restrict__ part, float* __restrict__ sent)
{
    const int d = blockIdx.x * 128 + threadIdx.x;
    const int b = blockIdx.y;
    float s = 0.f;
#pragma unroll
    for (int cc = 0; cc < 16; cc++) s += part[(size_t)(b * 16 + cc) * DMODEL + d];
    sent[(size_t)b * DMODEL + d] = s * (1.f / (float)SEQ);
}

// ---------------- loss ------------------------------------------------------
__global__ __launch_bounds__(1024) void loss_k(
    const float* __restrict__ sent, const int* __restrict__ y, float* __restrict__ out)
{
    __shared__ float red[1024];
    __shared__ float s_loss;
    const int tid = threadIdx.x;
    if (tid == 0) s_loss = 0.f;
    __syncthreads();

    for (int b = 0; b < BATCH; b++) {
        const float v = sent[(size_t)b * DMODEL + tid];
        red[tid] = v; __syncthreads();
        for (int s = 512; s > 0; s >>= 1) {
            if (tid < s) red[tid] = fmaxf(red[tid], red[tid + s]);
            __syncthreads();
        }
        const float mx = red[0]; __syncthreads();
        red[tid] = expf(v - mx); __syncthreads();
        for (int s = 512; s > 0; s >>= 1) {
            if (tid < s) red[tid] += red[tid + s];
            __syncthreads();
        }
        if (tid == 0) {
            const float lse = mx + logf(red[0]);
            s_loss += sent[(size_t)b * DMODEL + y[b]] - lse;
        }
        __syncthreads();
    }
    if (tid == 0) out[0] = -s_loss * (1.f / (float)BATCH);
}

// ---------------- launcher --------------------------------------------------
static void moe_layer(const __nv_bfloat16* act_in, const float* Wg,
                      const __nv_bfloat16* WeT, const float* be,
                      __nv_bfloat16* act_out,
                      int* p_idx, float* p_gval, float* p_gsc, int* p_inv, int* p_ccnt)
{
    gate_k    <<<TOKENS / 8, 256>>>(act_in, Wg, p_idx, p_gval);
    hist_k    <<<32, 256>>>(p_idx, p_ccnt);
    scan2_k   <<<1, 256>>>(p_ccnt);
    fillneg_k <<<(NEXP * CAP + 255) / 256, 256>>>(p_inv, NEXP * CAP);
    assign_k  <<<32, 256>>>(p_idx, p_gval, p_ccnt, p_gsc, p_inv);
    zerodropb_k<<<TOKENS, 128>>>(p_gsc, (uint4*)act_out);
    dim3 g(DMODEL / BN, CAP / BM, NEXP);
    bgemm_k<<<g, 256>>>(act_in, WeT, be, act_out, p_inv, p_gsc, CAP);
}

extern "C" void kernel_launch(void* const* d_in, const int* in_sizes, int n_in,
                              void* d_out, int out_size)
{
    const float* x   = (const float*)d_in[0];
    const int*   y   = (const int*)  d_in[1];
    const float* W1  = (const float*)d_in[2];
    const float* b1  = (const float*)d_in[3];
    const float* Wg2 = (const float*)d_in[4];
    const float* We2 = (const float*)d_in[5];
    const float* be2 = (const float*)d_in[6];
    const float* Wg3 = (const float*)d_in[7];
    const float* We3 = (const float*)d_in[8];
    const float* be3 = (const float*)d_in[9];
    float* out = (float*)d_out;

    __nv_bfloat16 *p_xb, *p_hb, *p_o2b, *p_o3b, *p_w1t, *p_w2t, *p_w3t;
    float *p_gval, *p_gsc, *p_part, *p_sent;
    int   *p_idx, *p_inv, *p_ccnt;
    cudaGetSymbolAddress((void**)&p_xb,   g_xb);
    cudaGetSymbolAddress((void**)&p_hb,   g_hb);
    cudaGetSymbolAddress((void**)&p_o2b,  g_o2b);
    cudaGetSymbolAddress((void**)&p_o3b,  g_o3b);
    cudaGetSymbolAddress((void**)&p_w1t,  g_w1t);
    cudaGetSymbolAddress((void**)&p_w2t,  g_w2t);
    cudaGetSymbolAddress((void**)&p_w3t,  g_w3t);
    cudaGetSymbolAddress((void**)&p_idx,  g_idx);
    cudaGetSymbolAddress((void**)&p_gval, g_gval);
    cudaGetSymbolAddress((void**)&p_gsc,  g_gsc);
    cudaGetSymbolAddress((void**)&p_inv,  g_inv);
    cudaGetSymbolAddress((void**)&p_ccnt, g_ccnt);
    cudaGetSymbolAddress((void**)&p_part, g_part);
    cudaGetSymbolAddress((void**)&p_sent, g_sent);

    // 0) convert x -> bf16; transpose+convert weights -> [e][n][k] bf16
    cvt_k<<<2048, 256>>>((const float4*)x, (uint4*)p_xb, TOKENS * DMODEL / 8);
    {
        dim3 tg(32, 32, 1);
        tconv_k<<<tg, 256>>>(W1, p_w1t);
        dim3 tge(32, 32, NEXP);
        tconv_k<<<tge, 256>>>(We2, p_w2t);
        tconv_k<<<tge, 256>>>(We3, p_w3t);
    }
    // 1) dense pre-layer: h = x @ W1 + b1   (bf16 out)
    {
        dim3 g(DMODEL / BN, TOKENS / BM, 1);
        bgemm_k<<<g, 256>>>(p_xb, p_w1t, b1, p_hb, nullptr, nullptr, TOKENS);
    }
    // 2) MoE layer 2: hb -> o2b
    moe_layer(p_hb, Wg2, p_w2t, be2, p_o2b, p_idx, p_gval, p_gsc, p_inv, p_ccnt);
    // 3) MoE layer 3: o2b -> o3b
    moe_layer(p_o2b, Wg3, p_w3t, be3, p_o3b, p_idx, p_gval, p_gsc, p_inv, p_ccnt);
    // 4) residual + mean over S
    {
        dim3 g1(DMODEL / 128, BATCH, 16);
        meanpartb_k<<<g1, 128>>>(p_hb, p_o3b, p_part);
        dim3 g2(DMODEL / 128, BATCH);
        meanfin_k<<<g2, 128>>>(p_part, p_sent);
    }
    // 5) loss
    loss_k<<<1, 1024>>>(p_sent, y, out);
}

// round 17
// speedup vs baseline: 5.9287x; 1.1369x over previous
#include <cuda_runtime.h>
#include <cuda_bf16.h>
#include <math.h>
#include <stdint.h>

// Problem constants
#define TOKENS  16384
#define DMODEL  1024
#define NEXP    8
#define CAP     2048
#define BATCH   8
#define SEQ     2048

// ---------------- scratch (device globals; no allocation allowed) ----------
__device__ __nv_bfloat16 g_xb [TOKENS * DMODEL];   // x in bf16
__device__ __nv_bfloat16 g_hb [TOKENS * DMODEL];   // dense layer out (bf16)
__device__ __nv_bfloat16 g_o2b[TOKENS * DMODEL];
__device__ __nv_bfloat16 g_o3b[TOKENS * DMODEL];
__device__ __nv_bfloat16 g_w1t[DMODEL * DMODEL];          // W1^T  [n][k] bf16
__device__ __nv_bfloat16 g_w2t[NEXP * DMODEL * DMODEL];   // We2^T [e][n][k]
__device__ __nv_bfloat16 g_w3t[NEXP * DMODEL * DMODEL];   // We3^T [e][n][k]
__device__ int   g_idx [TOKENS];
__device__ float g_gval[TOKENS];
__device__ float g_gsc [TOKENS];
__device__ int   g_inv [NEXP * CAP];
__device__ int   g_ccnt[256 * NEXP];
__device__ float g_part[BATCH * 16 * DMODEL];
__device__ float g_sent[BATCH * DMODEL];

// ---------------- low-level helpers ----------------------------------------
__device__ __forceinline__ void cp16(void* dst, const void* src, bool p) {
    unsigned s = (unsigned)__cvta_generic_to_shared(dst);
    int sz = p ? 16 : 0;
    asm volatile("cp.async.cg.shared.global [%0], [%1], 16, %2;\n"
                 :: "r"(s), "l"(src), "r"(sz) : "memory");
}
#define CP_COMMIT() asm volatile("cp.async.commit_group;\n" ::: "memory")
#define CP_WAIT(n)  asm volatile("cp.async.wait_group %0;\n" :: "n"(n) : "memory")

__device__ __forceinline__ uint32_t s2u(const void* p) {
    uint32_t r;
    asm("{ .reg .u64 t; cvta.to.shared.u64 t, %1; cvt.u32.u64 %0, t; }" : "=r"(r) : "l"(p));
    return r;
}

__device__ __forceinline__ void ldm_x4(uint32_t* r, uint32_t saddr) {
    asm volatile("ldmatrix.sync.aligned.m8n8.x4.shared.b16 {%0,%1,%2,%3}, [%4];"
                 : "=r"(r[0]), "=r"(r[1]), "=r"(r[2]), "=r"(r[3]) : "r"(saddr));
}

__device__ __forceinline__ void mma_bf16(float* d, const uint32_t* a, const uint32_t* b) {
    asm volatile(
        "mma.sync.aligned.m16n8k16.row.col.f32.bf16.bf16.f32 "
        "{%0,%1,%2,%3}, {%4,%5,%6,%7}, {%8,%9}, {%0,%1,%2,%3};\n"
        : "+f"(d[0]), "+f"(d[1]), "+f"(d[2]), "+f"(d[3])
        : "r"(a[0]), "r"(a[1]), "r"(a[2]), "r"(a[3]), "r"(b[0]), "r"(b[1]));
}

// ---------------- bf16 tensor-core GEMM (mma.sync + ldmatrix) ---------------
// C[t,n] = (gather(A)[m,:] @ Bt[e][n][:]^T + bias[e,n]) * scale[t]  (bf16 out)
// A: [rows][K] bf16 K-major. Bt: [e][n][k] bf16 K-major.
// rowmap==nullptr: dense. rowmap!=nullptr: A row = rowmap[z*M+m] (<0 => zero/skip),
// epilogue scatters to C[tok,:] scaled by scale[tok].
#define BM   128
#define BN   128
#define BKB  64
#define KROW 72            // padded row: 72 bf16 = 144 B (conflict-free ldmatrix)
#define TILE_ELEMS (128 * KROW)
#define SMEM_GEMM  (4 * TILE_ELEMS * 2)   // A0,A1,B0,B1 = 73728 B

__global__ __launch_bounds__(256, 2) void bgemm_k(
    const __nv_bfloat16* __restrict__ A,
    const __nv_bfloat16* __restrict__ Bt,
    const float* __restrict__ bias,
    __nv_bfloat16* __restrict__ C,
    const int* __restrict__ rowmap,
    const float* __restrict__ scale, int Mrows)
{
    extern __shared__ __nv_bfloat16 dsm[];
    __nv_bfloat16* Abuf[2] = { dsm,                  dsm + TILE_ELEMS };
    __nv_bfloat16* Bbuf[2] = { dsm + 2 * TILE_ELEMS, dsm + 3 * TILE_ELEMS };

    const int e = blockIdx.z;
    const __nv_bfloat16* Bm = Bt + (size_t)e * DMODEL * DMODEL;
    const float* bvec = bias + (size_t)e * DMODEL;
    const int* rmap = rowmap ? rowmap + (size_t)e * Mrows : nullptr;

    const int mBase = blockIdx.y * BM;
    const int nBase = blockIdx.x * BN;
    const int tid = threadIdx.x;

    // ---- global->smem mapping: per chunk each thread loads 4 A + 4 B segs (16B)
    const int sg = (tid & 7) * 8;             // k-elem offset within row
    int rowi[4]; bool ap[4];
    const __nv_bfloat16* aS[4];
    const __nv_bfloat16* bS[4];
#pragma unroll
    for (int i = 0; i < 4; i++) {
        rowi[i] = i * 32 + (tid >> 3);        // 0..127
        int tok = rmap ? rmap[mBase + rowi[i]] : (mBase + rowi[i]);
        ap[i] = tok >= 0;
        aS[i] = A  + (size_t)(ap[i] ? tok : 0) * DMODEL + sg;
        bS[i] = Bm + (size_t)(nBase + rowi[i]) * DMODEL + sg;
    }

    auto load_stage = [&](int k0, int b) {
#pragma unroll
        for (int i = 0; i < 4; i++) {
            cp16(Abuf[b] + rowi[i] * KROW + sg, aS[i] + k0, ap[i]);
            cp16(Bbuf[b] + rowi[i] * KROW + sg, bS[i] + k0, true);
        }
    };

    // ---- warp / fragment mapping: warp tile 64(M) x 32(N)
    const int wid = tid >> 5, lane = tid & 31;
    const int wm = (wid >> 2) * 64;
    const int wn = (wid & 3) * 32;
    const int r = lane >> 2;          // groupID 0..7
    const int c = lane & 3;           // threadID in group

    // ldmatrix lane address components
    const int aRowL = wm + (lane & 15);                            // + mi*16
    const int aColL = (lane >> 4) * 8;                             // + ks
    const int bRowL = wn + ((lane >> 4) << 3) + (lane & 7);        // + nip*16
    const int bColL = ((lane >> 3) & 1) * 8;                       // + ks

    float acc[4][4][4];
#pragma unroll
    for (int i = 0; i < 4; i++)
#pragma unroll
        for (int j = 0; j < 4; j++)
#pragma unroll
            for (int q = 0; q < 4; q++) acc[i][j][q] = 0.f;

    const int nk = DMODEL / BKB;      // 16 chunks
    load_stage(0, 0);
    CP_COMMIT();

    const uint32_t sAbase[2] = { s2u(Abuf[0]), s2u(Abuf[1]) };
    const uint32_t sBbase[2] = { s2u(Bbuf[0]), s2u(Bbuf[1]) };

    for (int kt = 0; kt < nk; kt++) {
        const int buf = kt & 1;
        if (kt + 1 < nk) {
            load_stage((kt + 1) * BKB, buf ^ 1);
            CP_COMMIT();
            CP_WAIT(1);
        } else {
            CP_WAIT(0);
        }
        __syncthreads();

        const uint32_t sA = sAbase[buf], sB = sBbase[buf];
#pragma unroll
        for (int ks = 0; ks < BKB; ks += 16) {
            uint32_t af[4][4], bfr[4][2];
#pragma unroll
            for (int mi = 0; mi < 4; mi++)
                ldm_x4(af[mi], sA + ((aRowL + mi * 16) * KROW + ks + aColL) * 2);
#pragma unroll
            for (int nip = 0; nip < 2; nip++)
                ldm_x4(&bfr[2 * nip][0], sB + ((bRowL + nip * 16) * KROW + ks + bColL) * 2);
#pragma unroll
            for (int mi = 0; mi < 4; mi++)
#pragma unroll
                for (int ni = 0; ni < 4; ni++)
                    mma_bf16(acc[mi][ni], af[mi], bfr[ni]);
        }
        __syncthreads();
    }

    // ---- epilogue: bias (+scale) -> bf16, (scatter-)store -------------------
    float bx[4], by[4];
#pragma unroll
    for (int ni = 0; ni < 4; ni++) {
        const int col = nBase + wn + ni * 8 + c * 2;
        bx[ni] = bvec[col]; by[ni] = bvec[col + 1];
    }
#pragma unroll
    for (int mi = 0; mi < 4; mi++) {
        const int mloc0 = mBase + wm + mi * 16 + r;
        const int mloc1 = mloc0 + 8;
        int orow0, orow1; float sc0 = 1.f, sc1 = 1.f;
        bool v0 = true, v1 = true;
        if (rmap) {
            const int t0 = rmap[mloc0], t1 = rmap[mloc1];
            v0 = t0 >= 0; v1 = t1 >= 0;
            orow0 = v0 ? t0 : 0; orow1 = v1 ? t1 : 0;
            if (v0) sc0 = scale[t0];
            if (v1) sc1 = scale[t1];
        } else {
            orow0 = mloc0; orow1 = mloc1;
        }
#pragma unroll
        for (int ni = 0; ni < 4; ni++) {
            const int col = nBase + wn + ni * 8 + c * 2;
            if (v0) {
                __nv_bfloat162 h2 = __float22bfloat162_rn(make_float2(
                    (acc[mi][ni][0] + bx[ni]) * sc0, (acc[mi][ni][1] + by[ni]) * sc0));
                *(uint32_t*)&C[(size_t)orow0 * DMODEL + col] = *(uint32_t*)&h2;
            }
            if (v1) {
                __nv_bfloat162 h2 = __float22bfloat162_rn(make_float2(
                    (acc[mi][ni][2] + bx[ni]) * sc1, (acc[mi][ni][3] + by[ni]) * sc1));
                *(uint32_t*)&C[(size_t)orow1 * DMODEL + col] = *(uint32_t*)&h2;
            }
        }
    }
}

// ---------------- fp32 -> bf16 convert (8 elems/thread/iter) ---------------
__global__ void cvt_k(const float4* __restrict__ src, uint4* __restrict__ dst, int n8)
{
    for (int i = blockIdx.x * blockDim.x + threadIdx.x; i < n8; i += gridDim.x * blockDim.x) {
        float4 a = src[2 * i], b = src[2 * i + 1];
        __nv_bfloat162 q0 = __float22bfloat162_rn(make_float2(a.x, a.y));
        __nv_bfloat162 q1 = __float22bfloat162_rn(make_float2(a.z, a.w));
        __nv_bfloat162 q2 = __float22bfloat162_rn(make_float2(b.x, b.y));
        __nv_bfloat162 q3 = __float22bfloat162_rn(make_float2(b.z, b.w));
        uint4 o;
        o.x = *(uint32_t*)&q0; o.y = *(uint32_t*)&q1;
        o.z = *(uint32_t*)&q2; o.w = *(uint32_t*)&q3;
        dst[i] = o;
    }
}

// ---------------- transpose + convert: dst[e][n][k] = bf16(src[e][k][n]) ----
__global__ __launch_bounds__(256) void tconv_k(
    const float* __restrict__ src, __nv_bfloat16* __restrict__ dst)
{
    __shared__ float t[32][33];
    const int e = blockIdx.z;
    src += (size_t)e * DMODEL * DMODEL;
    dst += (size_t)e * DMODEL * DMODEL;
    const int bx = blockIdx.x * 32, by = blockIdx.y * 32;
    const int tx = threadIdx.x & 31, ty = threadIdx.x >> 5;
#pragma unroll
    for (int i = 0; i < 4; i++)
        t[ty + 8 * i][tx] = src[(size_t)(by + ty + 8 * i) * DMODEL + bx + tx];
    __syncthreads();
#pragma unroll
    for (int i = 0; i < 4; i++)
        dst[(size_t)(bx + ty + 8 * i) * DMODEL + by + tx] =
            __float2bfloat16(t[tx][ty + 8 * i]);
}

// ---------------- gating: 8 tokens per warp, Wg staged once per block -------
__global__ __launch_bounds__(256) void gate_k(
    const __nv_bfloat16* __restrict__ act, const float* __restrict__ Wg,
    int* __restrict__ idx, float* __restrict__ gval)
{
    __shared__ float sWgT[NEXP][DMODEL];
    const int tid = threadIdx.x;
    for (int i = tid; i < DMODEL * NEXP; i += 256) {
        const int k = i >> 3, e = i & 7;
        sWgT[e][k] = Wg[i];
    }
    __syncthreads();

    const int w = tid >> 5, lane = tid & 31;
    for (int tt = 0; tt < 8; tt++) {
        const int t = blockIdx.x * 64 + w * 8 + tt;
        const __nv_bfloat16* arow = act + (size_t)t * DMODEL;

        float a8[NEXP];
#pragma unroll
        for (int e = 0; e < NEXP; e++) a8[e] = 0.f;
        for (int k = lane; k < DMODEL; k += 32) {
            const float a = __bfloat162float(arow[k]);
#pragma unroll
            for (int e = 0; e < NEXP; e++) a8[e] += a * sWgT[e][k];
        }
#pragma unroll
        for (int e = 0; e < NEXP; e++)
#pragma unroll
            for (int off = 16; off > 0; off >>= 1)
                a8[e] += __shfl_xor_sync(0xffffffffu, a8[e], off);

        if (lane == 0) {
            float mx = a8[0]; int am = 0;
#pragma unroll
            for (int e = 1; e < NEXP; e++)
                if (a8[e] > mx) { mx = a8[e]; am = e; }   // first-max ties == jnp.argmax
            float s = 0.f;
#pragma unroll
            for (int e = 0; e < NEXP; e++) s += __expf(a8[e] - mx);
            idx[t]  = am;
            gval[t] = 1.f / s;
        }
    }
}

// ---------------- capacity assignment: hist -> scan -> assign ---------------
__global__ __launch_bounds__(256) void hist_k(
    const int* __restrict__ idx, int* __restrict__ ccnt)
{
    const int gw   = (blockIdx.x * 256 + threadIdx.x) >> 5;
    const int lane = threadIdx.x & 31;
    const int t0 = gw * 64;
    const int e0 = idx[t0 + lane], e1 = idx[t0 + 32 + lane];
    int cnt[NEXP];
#pragma unroll
    for (int e = 0; e < NEXP; e++) {
        unsigned m0 = __ballot_sync(0xffffffffu, e0 == e);
        unsigned m1 = __ballot_sync(0xffffffffu, e1 == e);
        cnt[e] = __popc(m0) + __popc(m1);
    }
    if (lane < NEXP) ccnt[gw * NEXP + lane] = cnt[lane];
}

__global__ __launch_bounds__(256) void scan2_k(int* __restrict__ ccnt)
{
    const int e = threadIdx.x >> 5, lane = threadIdx.x & 31;
    int carry = 0;
    for (int c0 = 0; c0 < 256; c0 += 32) {
        int v = ccnt[(c0 + lane) * NEXP + e];
        int s = v;
#pragma unroll
        for (int off = 1; off < 32; off <<= 1) {
            int n = __shfl_up_sync(0xffffffffu, s, off);
            if (lane >= off) s += n;
        }
        ccnt[(c0 + lane) * NEXP + e] = carry + s - v;
        carry += __shfl_sync(0xffffffffu, s, 31);
    }
}

__global__ __launch_bounds__(256) void assign_k(
    const int* __restrict__ idx, const float* __restrict__ gval,
    const int* __restrict__ ccnt, float* __restrict__ gsc,
    int* __restrict__ invmap)
{
    const int gw   = (blockIdx.x * 256 + threadIdx.x) >> 5;
    const int lane = threadIdx.x & 31;
    const int t0 = gw * 64;
    const int ta = t0 + lane, tb = t0 + 32 + lane;
    const int e0 = idx[ta], e1 = idx[tb];
    const unsigned lt = (1u << lane) - 1u;
    int rank0 = 0, rank1 = 0;
#pragma unroll
    for (int e = 0; e < NEXP; e++) {
        unsigned m0 = __ballot_sync(0xffffffffu, e0 == e);
        unsigned m1 = __ballot_sync(0xffffffffu, e1 == e);
        if (e0 == e) rank0 = __popc(m0 & lt);
        if (e1 == e) rank1 = __popc(m0) + __popc(m1 & lt);
    }
    const int loc0 = ccnt[gw * NEXP + e0] + rank0;
    const int loc1 = ccnt[gw * NEXP + e1] + rank1;
    if (loc0 < CAP) { gsc[ta] = gval[ta]; invmap[e0 * CAP + loc0] = ta; }
    else            { gsc[ta] = 0.f; }
    if (loc1 < CAP) { gsc[tb] = gval[tb]; invmap[e1 * CAP + loc1] = tb; }
    else            { gsc[tb] = 0.f; }
}

// ---------------- utility kernels -----------------------------------------
__global__ void fillneg_k(int* __restrict__ p, int n) {
    int i = blockIdx.x * blockDim.x + threadIdx.x;
    if (i < n) p[i] = -1;
}
__global__ __launch_bounds__(128) void zerodropb_k(
    const float* __restrict__ gsc, uint4* __restrict__ out)
{
    const int t = blockIdx.x;
    if (gsc[t] != 0.f) return;
    const uint4 z = make_uint4(0, 0, 0, 0);
    uint4* row = out + (size_t)t * (DMODEL / 8);   // 1024 bf16 = 128 x uint4
    row[threadIdx.x] = z;
}

// ---------------- residual + mean over S (bf16 inputs) ----------------------
__global__ __launch_bounds__(128) void meanpartb_k(
    const __nv_bfloat16* __restrict__ h, const __nv_bfloat16* __restrict__ o,
    float* __restrict__ part)
{
    const int d = blockIdx.x * 128 + threadIdx.x;
    const int b = blockIdx.y, sc = blockIdx.z;
    const int base = b * SEQ + sc * 128;
    float s = 0.f;
#pragma unroll 4
    for (int rr = 0; rr < 128; rr++) {
        const size_t off = (size_t)(base + rr) * DMODEL + d;
        s += __bfloat162float(h[off]) + __bfloat162float(o[off]);
    }
    part[(size_t)(b * 16 + sc) * DMODEL + d] = s;
}
__global__ __launch_bounds__(128) void meanfin_k(
    const float* __restrict__ part, float* __restrict__ sent)
{
    const int d = blockIdx.x * 128 + threadIdx.x;
    const int b = blockIdx.y;
    float s = 0.f;
#pragma unroll
    for (int cc = 0; cc < 16; cc++) s += part[(size_t)(b * 16 + cc) * DMODEL + d];
    sent[(size_t)b * DMODEL + d] = s * (1.f / (float)SEQ);
}

// ---------------- loss ------------------------------------------------------
__global__ __launch_bounds__(1024) void loss_k(
    const float* __restrict__ sent, const int* __restrict__ y, float* __restrict__ out)
{
    __shared__ float red[1024];
    __shared__ float s_loss;
    const int tid = threadIdx.x;
    if (tid == 0) s_loss = 0.f;
    __syncthreads();

    for (int b = 0; b < BATCH; b++) {
        const float v = sent[(size_t)b * DMODEL + tid];
        red[tid] = v; __syncthreads();
        for (int s = 512; s > 0; s >>= 1) {
            if (tid < s) red[tid] = fmaxf(red[tid], red[tid + s]);
            __syncthreads();
        }
        const float mx = red[0]; __syncthreads();
        red[tid] = expf(v - mx); __syncthreads();
        for (int s = 512; s > 0; s >>= 1) {
            if (tid < s) red[tid] += red[tid + s];
            __syncthreads();
        }
        if (tid == 0) {
            const float lse = mx + logf(red[0]);
            s_loss += sent[(size_t)b * DMODEL + y[b]] - lse;
        }
        __syncthreads();
    }
    if (tid == 0) out[0] = -s_loss * (1.f / (float)BATCH);
}

// ---------------- launcher --------------------------------------------------
static void moe_layer(const __nv_bfloat16* act_in, const float* Wg,
                      const __nv_bfloat16* WeT, const float* be,
                      __nv_bfloat16* act_out,
                      int* p_idx, float* p_gval, float* p_gsc, int* p_inv, int* p_ccnt)
{
    gate_k    <<<TOKENS / 64, 256>>>(act_in, Wg, p_idx, p_gval);
    hist_k    <<<32, 256>>>(p_idx, p_ccnt);
    scan2_k   <<<1, 256>>>(p_ccnt);
    fillneg_k <<<(NEXP * CAP + 255) / 256, 256>>>(p_inv, NEXP * CAP);
    assign_k  <<<32, 256>>>(p_idx, p_gval, p_ccnt, p_gsc, p_inv);
    zerodropb_k<<<TOKENS, 128>>>(p_gsc, (uint4*)act_out);
    dim3 g(DMODEL / BN, CAP / BM, NEXP);
    bgemm_k<<<g, 256, SMEM_GEMM>>>(act_in, WeT, be, act_out, p_inv, p_gsc, CAP);
}

extern "C" void kernel_launch(void* const* d_in, const int* in_sizes, int n_in,
                              void* d_out, int out_size)
{
    const float* x   = (const float*)d_in[0];
    const int*   y   = (const int*)  d_in[1];
    const float* W1  = (const float*)d_in[2];
    const float* b1  = (const float*)d_in[3];
    const float* Wg2 = (const float*)d_in[4];
    const float* We2 = (const float*)d_in[5];
    const float* be2 = (const float*)d_in[6];
    const float* Wg3 = (const float*)d_in[7];
    const float* We3 = (const float*)d_in[8];
    const float* be3 = (const float*)d_in[9];
    float* out = (float*)d_out;

    __nv_bfloat16 *p_xb, *p_hb, *p_o2b, *p_o3b, *p_w1t, *p_w2t, *p_w3t;
    float *p_gval, *p_gsc, *p_part, *p_sent;
    int   *p_idx, *p_inv, *p_ccnt;
    cudaGetSymbolAddress((void**)&p_xb,   g_xb);
    cudaGetSymbolAddress((void**)&p_hb,   g_hb);
    cudaGetSymbolAddress((void**)&p_o2b,  g_o2b);
    cudaGetSymbolAddress((void**)&p_o3b,  g_o3b);
    cudaGetSymbolAddress((void**)&p_w1t,  g_w1t);
    cudaGetSymbolAddress((void**)&p_w2t,  g_w2t);
    cudaGetSymbolAddress((void**)&p_w3t,  g_w3t);
    cudaGetSymbolAddress((void**)&p_idx,  g_idx);
    cudaGetSymbolAddress((void**)&p_gval, g_gval);
    cudaGetSymbolAddress((void**)&p_gsc,  g_gsc);
    cudaGetSymbolAddress((void**)&p_inv,  g_inv);
    cudaGetSymbolAddress((void**)&p_ccnt, g_ccnt);
    cudaGetSymbolAddress((void**)&p_part, g_part);
    cudaGetSymbolAddress((void**)&p_sent, g_sent);

    // dynamic smem opt-in (host-side, unconditional, capture-safe)
    cudaFuncSetAttribute(bgemm_k, cudaFuncAttributeMaxDynamicSharedMemorySize, SMEM_GEMM);

    // 0) convert x -> bf16; transpose+convert weights -> [e][n][k] bf16
    cvt_k<<<2048, 256>>>((const float4*)x, (uint4*)p_xb, TOKENS * DMODEL / 8);
    {
        dim3 tg(32, 32, 1);
        tconv_k<<<tg, 256>>>(W1, p_w1t);
        dim3 tge(32, 32, NEXP);
        tconv_k<<<tge, 256>>>(We2, p_w2t);
        tconv_k<<<tge, 256>>>(We3, p_w3t);
    }
    // 1) dense pre-layer: h = x @ W1 + b1   (bf16 out)
    {
        dim3 g(DMODEL / BN, TOKENS / BM, 1);
        bgemm_k<<<g, 256, SMEM_GEMM>>>(p_xb, p_w1t, b1, p_hb, nullptr, nullptr, TOKENS);
    }
    // 2) MoE layer 2: hb -> o2b
    moe_layer(p_hb, Wg2, p_w2t, be2, p_o2b, p_idx, p_gval, p_gsc, p_inv, p_ccnt);
    // 3) MoE layer 3: o2b -> o3b
    moe_layer(p_o2b, Wg3, p_w3t, be3, p_o3b, p_idx, p_gval, p_gsc, p_inv, p_ccnt);
    // 4) residual + mean over S
    {
        dim3 g1(DMODEL / 128, BATCH, 16);
        meanpartb_k<<<g1, 128>>>(p_hb, p_o3b, p_part);
        dim3 g2(DMODEL / 128, BATCH);
        meanfin_k<<<g2, 128>>>(p_part, p_sent);
    }
    // 5) loss
    loss_k<<<1, 1024>>>(p_sent, y, out);
}